// round 6
// baseline (speedup 1.0000x reference)
#include <cuda_runtime.h>

#define B        1024
#define NUM_VARS 2048
#define LEAVES   (2 * NUM_VARS)            // 4096
#define LEVELS   12
#define WIDTH    4096
#define NINT     (LEVELS * WIDTH)          // 49152 internal nodes
#define TOTAL    (LEAVES + NINT)           // 53248

#define NTHR     256
#define BBK      8                 // batch columns per block
#define NLANE    32                // node lanes in forward
#define NBLK     (B / BBK)         // 128 blocks

#define LIST_CAP 128               // plan entries per level in smem
#define VCAP     512               // compact internal values in smem
#define VPAD     9
#define XPAD     2052              // xrow stride (floats): 16B-aligned, bank-staggered

// ---------------------------------------------------------------------------
// Global spill scratch (worst-case fallback; normally untouched).
// ---------------------------------------------------------------------------
__device__ float g_val[(size_t)NINT * B];            // [cid][b] overflow values
__device__ int2  g_hdr_spill[NBLK][LEVELS][WIDTH];   // {orig id, cid}/{cid|op}
__device__ int4  g_ch_spill[NBLK][LEVELS][WIDTH];    // resolved operands

// smem layout (bytes)
#define SM_BITS 0                                   // uint[1536]        6144
#define SM_CMAP 6144                                // ushort[NINT]     98304
#define SM_HDR  (SM_CMAP + NINT * 2)                // int2[12][128]    12288
#define SM_CH   (SM_HDR + LEVELS * LIST_CAP * 8)    // int4[12][128]    24576
#define SM_VAL  (SM_CH + LEVELS * LIST_CAP * 16)    // float[512*9]     18432
#define SM_XROW (SM_VAL + VCAP * VPAD * 4)          // float[8*2052]    65664
#define SM_TOTAL (SM_XROW + BBK * XPAD * 4)         // 225408 B

// ---------------------------------------------------------------------------
// One kernel, one wave. Per block:
//   warp 0     : backward discovery -> fully-resolved plan (no block barriers)
//   warps 1..7 : concurrently stage this block's 8 x-rows into smem
//   join (__syncthreads), then 12 forward levels (1 bar each), all-SMEM.
// Operand encoding: bit31 set -> leaf (id in low bits, id>=2048 means 1-x);
// otherwise compact internal id (smem val if < VCAP, else g_val).
// ---------------------------------------------------------------------------
__global__ void __launch_bounds__(NTHR, 1)
eval_all(const float* __restrict__ x,
         const int*   __restrict__ child_idx,
         const int*   __restrict__ op_type,
         float*       __restrict__ out)
{
    extern __shared__ unsigned char sm[];
    unsigned int*   bits = (unsigned int*)  (sm + SM_BITS);
    unsigned short* cmap = (unsigned short*)(sm + SM_CMAP);
    int2*           hdr  = (int2*)          (sm + SM_HDR);
    int4*           chv  = (int4*)          (sm + SM_CH);
    float*          val  = (float*)         (sm + SM_VAL);
    float*          xrow = (float*)         (sm + SM_XROW);

    __shared__ int scnt[LEVELS];
    __shared__ int snnodes;

    const int tid = threadIdx.x;
    const int blk = blockIdx.x;

    if (tid < 32) {
        // ================= warp 0: discovery =================
        const int lane = tid;
        for (int i = lane; i < NINT / 32; i += 32) bits[i] = 0u;
        if (lane < LEVELS) scnt[lane] = 0;
        __syncwarp();
        if (lane == 0) {
            snnodes = 1;                                   // root = cid 0
            hdr[(LEVELS - 1) * LIST_CAP] = make_int2(TOTAL - 1, 0);
            scnt[LEVELS - 1] = 1;
            const int ri = (TOTAL - 1) - LEAVES;           // 49151
            bits[ri >> 5] = 1u << (ri & 31);
            cmap[ri] = 0;
        }
        __syncwarp();

        for (int l = LEVELS - 1; l >= 0; --l) {
            const int cnt = scnt[l];
            for (int ibase = 0; ibase < cnt; ibase += 32) {
                const int i = ibase + lane;
                int2 h; int4 ch; int myop = 0;
                // ---- phase A: claim children, assign cids ----
                if (i < cnt) {
                    h = (i < LIST_CAP) ? hdr[l * LIST_CAP + i]
                                       : g_hdr_spill[blk][l][i];
                    const int w = h.x - LEAVES - l * WIDTH;
                    ch   = ((const int4*)child_idx)[l * WIDTH + w];
                    myop = op_type[l * WIDTH + w];
                    const int cs[4] = {ch.x, ch.y, ch.z, ch.w};
                    #pragma unroll
                    for (int f = 0; f < 4; ++f) {
                        const int c = cs[f];
                        if (c >= LEAVES) {                 // internal child
                            const int ci = c - LEAVES;
                            const unsigned int m = 1u << (ci & 31);
                            const unsigned int old = atomicOr(&bits[ci >> 5], m);
                            if (!(old & m)) {              // first discoverer
                                const int cid = atomicAdd(&snnodes, 1);
                                cmap[ci] = (unsigned short)cid;
                                const int ll  = ci >> 12;  // / WIDTH
                                const int pos = atomicAdd(&scnt[ll], 1);
                                if (pos < LIST_CAP)
                                    hdr[ll * LIST_CAP + pos] = make_int2(c, cid);
                                else
                                    g_hdr_spill[blk][ll][pos] = make_int2(c, cid);
                            }
                        } // leaves need no scheduling
                    }
                }
                __syncwarp();
                // ---- phase B: emit resolved plan entry ----
                if (i < cnt) {
                    int4 rc;
                    #define ENC(c) ((c) < LEAVES ? (int)(0x80000000u | (unsigned)(c)) \
                                                 : (int)cmap[(c) - LEAVES])
                    rc.x = ENC(ch.x); rc.y = ENC(ch.y);
                    rc.z = ENC(ch.z); rc.w = ENC(ch.w);
                    #undef ENC
                    const int2 h2 = make_int2(h.x, h.y | (myop << 31));
                    if (i < LIST_CAP) {
                        chv[l * LIST_CAP + i] = rc;
                        hdr[l * LIST_CAP + i] = h2;
                    } else {
                        g_ch_spill[blk][l][i]  = rc;
                        g_hdr_spill[blk][l][i] = h2;
                    }
                }
                __syncwarp();
            }
        }
    } else {
        // ============ warps 1..7: stage x rows into smem ============
        // 8 rows x 2048 floats = 4096 float4 loads, coalesced.
        for (int idx = tid - 32; idx < (BBK * NUM_VARS) / 4; idx += NTHR - 32) {
            const int r  = idx >> 9;          // / 512 float4 per row
            const int c4 = idx & 511;
            const float4 v = ((const float4*)x)[(size_t)(blk * BBK + r) * (NUM_VARS / 4) + c4];
            *(float4*)&xrow[r * XPAD + c4 * 4] = v;
        }
    }
    __syncthreads();   // join: plan + xrow ready for everyone

    // ================= forward evaluation =================
    const int bb   = tid & (BBK - 1);
    const int lane = tid >> 3;                // 0..31
    const int bg   = blk * BBK + bb;

    for (int l = 0; l < LEVELS; ++l) {
        const int cnt = scnt[l];
        for (int i = lane; i < cnt; i += NLANE) {
            const int2 h = (i < LIST_CAP) ? hdr[l * LIST_CAP + i]
                                          : g_hdr_spill[blk][l][i];
            const int4 e = (i < LIST_CAP) ? chv[l * LIST_CAP + i]
                                          : g_ch_spill[blk][l][i];
            const int dest = h.y & 0x7FFFFFFF;
            const int op   = ((unsigned)h.y) >> 31;
            #define FETCH(c) ((c) < 0                                            \
                ? (((c) & 0x7FFFFFFF) < NUM_VARS                                 \
                    ? xrow[bb * XPAD + ((c) & (NUM_VARS - 1))]                   \
                    : 1.0f - xrow[bb * XPAD + ((c) & (NUM_VARS - 1))])           \
                : ((c) < VCAP ? val[(c) * VPAD + bb]                             \
                              : g_val[(size_t)(c) * B + bg]))
            const float v0 = FETCH(e.x);
            const float v1 = FETCH(e.y);
            const float v2 = FETCH(e.z);
            const float v3 = FETCH(e.w);
            #undef FETCH
            const float r = op ? (v0 + v1) + (v2 + v3)
                               : (v0 * v1) * (v2 * v3);
            if (dest < VCAP) val[dest * VPAD + bb] = r;
            else             g_val[(size_t)dest * B + bg] = r;
        }
        __syncthreads();
    }

    if (lane == 0) out[bg] = val[bb];          // root has cid 0 (< VCAP)
}

// ---------------------------------------------------------------------------
// Launch: x (f32), child_idx (i32), op_type (i32). One kernel; capturable.
// ---------------------------------------------------------------------------
extern "C" void kernel_launch(void* const* d_in, const int* in_sizes, int n_in,
                              void* d_out, int out_size) {
    const float* x         = (const float*)d_in[0];
    const int*   child_idx = (const int*)  d_in[1];
    const int*   op_type   = (const int*)  d_in[2];
    float*       out       = (float*)d_out;

    cudaFuncSetAttribute(eval_all,
                         cudaFuncAttributeMaxDynamicSharedMemorySize, SM_TOTAL);
    eval_all<<<NBLK, NTHR, SM_TOTAL>>>(x, child_idx, op_type, out);
}